// round 15
// baseline (speedup 1.0000x reference)
#include <cuda_runtime.h>
#include <cuda_fp16.h>
#include <cstdint>
#include <cstddef>

#define B_ 8
#define N_ 512
#define T_ 2048
#define E_ 4096
#define D_ 768
#define TD_ 128
#define L_ 4
#define F_ (TD_ + D_)   /* 896 */
#define G_ (3 * D_)     /* 2304 */
#define M_ (B_ * N_)    /* 4096 */
#define TPN_ (T_ / N_)  /* 4 tokens per node */
#define LD_ (L_ * D_)   /* 3072 */

// ---------------- fp32 scratch ----------------
__device__ float g_fused[M_ * F_];
__device__ float g_h    [M_ * D_];
__device__ float g_q    [M_ * D_];      // q = gather(h)
__device__ float g_gi   [M_ * G_];
__device__ float g_gh   [M_ * G_];

// ---------------- CSR scratch ----------------
__device__ int   g_cnt  [B_ * N_];
__device__ int   g_off  [B_ * (N_ + 1)];
__device__ int   g_pos  [B_ * N_];
__device__ int   g_src_s[B_ * E_];
__device__ float g_w_s  [B_ * E_];

// ---------------- fp16 weights (K-major) ----------------
__device__ __half s_fw  [D_ * F_];        // fusion_w^T  [768][896]
__device__ __half s_gwnt[L_ * D_ * D_];   // ggnn_w plain fp16 (= [3072][768] B op)
__device__ __half s_hh  [G_ * D_];        // w_hh [2304][768]
__device__ __half s_wc16[L_ * G_ * D_];   // Wc^T fp16 [l][2304][768]

// ================= helpers =================
__device__ __forceinline__ uint32_t smem_u32(const void* p) {
    uint32_t a;
    asm("{ .reg .u64 t; cvta.to.shared.u64 t, %1; cvt.u32.u64 %0, t; }" : "=r"(a) : "l"(p));
    return a;
}
__device__ __forceinline__ void cp16(uint32_t saddr, const void* g) {
    asm volatile("cp.async.cg.shared.global [%0], [%1], 16;" :: "r"(saddr), "l"(g) : "memory");
}
#define CP_COMMIT() asm volatile("cp.async.commit_group;" ::: "memory")
#define CP_WAIT1()  asm volatile("cp.async.wait_group 1;" ::: "memory")

__device__ __forceinline__ void ldsm4(uint32_t& r0, uint32_t& r1, uint32_t& r2,
                                      uint32_t& r3, uint32_t a) {
    asm volatile("ldmatrix.sync.aligned.m8n8.x4.shared.b16 {%0,%1,%2,%3}, [%4];"
                 : "=r"(r0), "=r"(r1), "=r"(r2), "=r"(r3) : "r"(a));
}
__device__ __forceinline__ void mma16816(float* d, const uint32_t* a, const uint32_t* b) {
    asm volatile(
        "mma.sync.aligned.m16n8k16.row.col.f32.f16.f16.f32 "
        "{%0,%1,%2,%3}, {%4,%5,%6,%7}, {%8,%9}, {%0,%1,%2,%3};"
        : "+f"(d[0]), "+f"(d[1]), "+f"(d[2]), "+f"(d[3])
        : "r"(a[0]), "r"(a[1]), "r"(a[2]), "r"(a[3]), "r"(b[0]), "r"(b[1]));
}

// 8 fp32 -> 4x half2 hi + 4x half2 lo (packed)
__device__ __forceinline__ void cvt8(float4 f0, float4 f1, uint4& H, uint4& Lo) {
    __half2 h0 = __floats2half2_rn(f0.x, f0.y);
    __half2 h1 = __floats2half2_rn(f0.z, f0.w);
    __half2 h2 = __floats2half2_rn(f1.x, f1.y);
    __half2 h3 = __floats2half2_rn(f1.z, f1.w);
    __half2 l0 = __floats2half2_rn(f0.x - __half2float(h0.x), f0.y - __half2float(h0.y));
    __half2 l1 = __floats2half2_rn(f0.z - __half2float(h1.x), f0.w - __half2float(h1.y));
    __half2 l2 = __floats2half2_rn(f1.x - __half2float(h2.x), f1.y - __half2float(h2.y));
    __half2 l3 = __floats2half2_rn(f1.z - __half2float(h3.x), f1.w - __half2float(h3.y));
    H.x  = *(uint32_t*)&h0; H.y  = *(uint32_t*)&h1; H.z  = *(uint32_t*)&h2; H.w  = *(uint32_t*)&h3;
    Lo.x = *(uint32_t*)&l0; Lo.y = *(uint32_t*)&l1; Lo.z = *(uint32_t*)&l2; Lo.w = *(uint32_t*)&l3;
}

// smem tile: 128 rows x 32 halves (64B) + 16B pad -> 80B row stride
#define ROWB    80
#define TILEB   (128 * ROWB)          /* 10240 */
#define STAGEB  (3 * TILEB)           /* Ahi, Alo, B = 30720 */
#define STAGES  3
#define SMEM_SZ (STAGES * STAGEB)     /* 92160; x2 CTAs = 184320 <= SM smem */

// ======== bmma: fp32-A 2-term fp16 GEMM; 3-stage depth-2 prefetch, 2 CTA/SM ==
__global__ void __launch_bounds__(256, 2) bmma(
    const float* __restrict__ A, const __half* __restrict__ Bh,
    const float* __restrict__ bias, float* __restrict__ C, int N, int K)
{
    extern __shared__ char smem[];
    const uint32_t sbase = smem_u32(smem);
    const int tid = threadIdx.x;
    const int wid = tid >> 5, lane = tid & 31;
    const int wm = wid & 3, wn = wid >> 2;
    const int bn = blockIdx.x, bm = blockIdx.y;
    const int nkc = K >> 5;

    const int lrow0 = tid >> 2;
    const int lrow1 = 64 + (tid >> 2);
    const int lseg  = tid & 3;
    const int ar = tid >> 1;
    const int asg = tid & 1;

    auto load_stage = [&](int stage, int kc) {   // prologue only
        uint32_t sb = sbase + stage * STAGEB;
        int kof = kc * 32;
        cp16(sb + 2 * TILEB + lrow0 * ROWB + lseg * 16,
             Bh + (size_t)(bn * 128 + lrow0) * K + kof + lseg * 8);
        cp16(sb + 2 * TILEB + lrow1 * ROWB + lseg * 16,
             Bh + (size_t)(bn * 128 + lrow1) * K + kof + lseg * 8);
        CP_COMMIT();
        const float4* Ap = (const float4*)(A + (size_t)(bm * 128 + ar) * K + kof + asg * 16);
        float4 f0 = Ap[0], f1 = Ap[1], f2 = Ap[2], f3 = Ap[3];
        uint4 H0, L0, H1, L1;
        cvt8(f0, f1, H0, L0);
        cvt8(f2, f3, H1, L1);
        char* arow = smem + stage * STAGEB + ar * ROWB + asg * 32;
        *(uint4*)(arow)              = H0;
        *(uint4*)(arow + 16)         = H1;
        *(uint4*)(arow + TILEB)      = L0;
        *(uint4*)(arow + TILEB + 16) = L1;
    };

    float acc[2][8][4];
    #pragma unroll
    for (int i = 0; i < 2; i++)
        #pragma unroll
        for (int j = 0; j < 8; j++)
            #pragma unroll
            for (int q = 0; q < 4; q++) acc[i][j][q] = 0.f;

    load_stage(0, 0);
    load_stage(1, 1);

    const int a_row  = wm * 32 + (lane & 15);
    const int a_colb = (lane >> 4) * 16;
    const int b_row  = wn * 64 + (lane & 7) + ((lane >> 4) << 3);
    const int b_colb = ((lane >> 3) & 1) * 16;

    for (int kc = 0; kc < nkc; kc++) {
        const bool pf = (kc + 2 < nkc);
        float4 f0, f1, f2, f3;
        const int st2 = (kc + 2) % STAGES;   // freed by previous iter's bottom sync
        if (pf) {
            uint32_t sb = sbase + st2 * STAGEB;
            int kof = (kc + 2) * 32;
            cp16(sb + 2 * TILEB + lrow0 * ROWB + lseg * 16,
                 Bh + (size_t)(bn * 128 + lrow0) * K + kof + lseg * 8);
            cp16(sb + 2 * TILEB + lrow1 * ROWB + lseg * 16,
                 Bh + (size_t)(bn * 128 + lrow1) * K + kof + lseg * 8);
            CP_COMMIT();
            const float4* Ap = (const float4*)(A + (size_t)(bm * 128 + ar) * K + kof + asg * 16);
            f0 = Ap[0]; f1 = Ap[1]; f2 = Ap[2]; f3 = Ap[3];
        }

        CP_WAIT1();
        __syncthreads();
        uint32_t st = sbase + (kc % STAGES) * STAGEB;
        uint32_t sah = st, sal = st + TILEB, sbh = st + 2 * TILEB;

        #pragma unroll
        for (int ks = 0; ks < 2; ks++) {
            uint32_t ah[2][4], al[2][4], b[8][2];
            #pragma unroll
            for (int mi = 0; mi < 2; mi++)
                ldsm4(ah[mi][0], ah[mi][1], ah[mi][2], ah[mi][3],
                      sah + (a_row + mi * 16) * ROWB + ks * 32 + a_colb);
            #pragma unroll
            for (int np = 0; np < 4; np++) {
                uint32_t r0, r1, r2, r3;
                ldsm4(r0, r1, r2, r3, sbh + (b_row + np * 16) * ROWB + ks * 32 + b_colb);
                b[np * 2 + 0][0] = r0; b[np * 2 + 0][1] = r1;
                b[np * 2 + 1][0] = r2; b[np * 2 + 1][1] = r3;
            }
            #pragma unroll
            for (int mi = 0; mi < 2; mi++)
                #pragma unroll
                for (int ni = 0; ni < 8; ni++)
                    mma16816(acc[mi][ni], ah[mi], b[ni]);
            #pragma unroll
            for (int mi = 0; mi < 2; mi++)
                ldsm4(al[mi][0], al[mi][1], al[mi][2], al[mi][3],
                      sal + (a_row + mi * 16) * ROWB + ks * 32 + a_colb);
            #pragma unroll
            for (int mi = 0; mi < 2; mi++)
                #pragma unroll
                for (int ni = 0; ni < 8; ni++)
                    mma16816(acc[mi][ni], al[mi], b[ni]);
        }

        if (pf) {
            uint4 H0, L0, H1, L1;
            cvt8(f0, f1, H0, L0);
            cvt8(f2, f3, H1, L1);
            char* arow = smem + st2 * STAGEB + ar * ROWB + asg * 32;
            *(uint4*)(arow)              = H0;
            *(uint4*)(arow + 16)         = H1;
            *(uint4*)(arow + TILEB)      = L0;
            *(uint4*)(arow + TILEB + 16) = L1;
        }
        __syncthreads();
    }

    const int r0 = bm * 128 + wm * 32 + (lane >> 2);
    const int c0 = bn * 128 + wn * 64 + (lane & 3) * 2;
    #pragma unroll
    for (int mi = 0; mi < 2; mi++) {
        #pragma unroll
        for (int ni = 0; ni < 8; ni++) {
            int col = c0 + ni * 8;
            float bx = 0.f, by = 0.f;
            if (bias) { bx = bias[col]; by = bias[col + 1]; }
            *(float2*)(C + (size_t)(r0 + mi * 16) * N + col) =
                make_float2(acc[mi][ni][0] + bx, acc[mi][ni][1] + by);
            *(float2*)(C + (size_t)(r0 + mi * 16 + 8) * N + col) =
                make_float2(acc[mi][ni][2] + bx, acc[mi][ni][3] + by);
        }
    }
}

// ======== bmma_wc: same mainloop, direct fp16 re-strided epilogue ========
__global__ void __launch_bounds__(256, 2) bmma_wc(
    const float* __restrict__ A, const __half* __restrict__ Bh,
    __half* __restrict__ wc16, int N, int K)
{
    extern __shared__ char smem[];
    const uint32_t sbase = smem_u32(smem);
    const int tid = threadIdx.x;
    const int wid = tid >> 5, lane = tid & 31;
    const int wm = wid & 3, wn = wid >> 2;
    const int bn = blockIdx.x, bm = blockIdx.y;
    const int nkc = K >> 5;

    const int lrow0 = tid >> 2;
    const int lrow1 = 64 + (tid >> 2);
    const int lseg  = tid & 3;
    const int ar = tid >> 1;
    const int asg = tid & 1;

    auto load_stage = [&](int stage, int kc) {
        uint32_t sb = sbase + stage * STAGEB;
        int kof = kc * 32;
        cp16(sb + 2 * TILEB + lrow0 * ROWB + lseg * 16,
             Bh + (size_t)(bn * 128 + lrow0) * K + kof + lseg * 8);
        cp16(sb + 2 * TILEB + lrow1 * ROWB + lseg * 16,
             Bh + (size_t)(bn * 128 + lrow1) * K + kof + lseg * 8);
        CP_COMMIT();
        const float4* Ap = (const float4*)(A + (size_t)(bm * 128 + ar) * K + kof + asg * 16);
        float4 f0 = Ap[0], f1 = Ap[1], f2 = Ap[2], f3 = Ap[3];
        uint4 H0, L0, H1, L1;
        cvt8(f0, f1, H0, L0);
        cvt8(f2, f3, H1, L1);
        char* arow = smem + stage * STAGEB + ar * ROWB + asg * 32;
        *(uint4*)(arow)              = H0;
        *(uint4*)(arow + 16)         = H1;
        *(uint4*)(arow + TILEB)      = L0;
        *(uint4*)(arow + TILEB + 16) = L1;
    };

    float acc[2][8][4];
    #pragma unroll
    for (int i = 0; i < 2; i++)
        #pragma unroll
        for (int j = 0; j < 8; j++)
            #pragma unroll
            for (int q = 0; q < 4; q++) acc[i][j][q] = 0.f;

    load_stage(0, 0);
    load_stage(1, 1);

    const int a_row  = wm * 32 + (lane & 15);
    const int a_colb = (lane >> 4) * 16;
    const int b_row  = wn * 64 + (lane & 7) + ((lane >> 4) << 3);
    const int b_colb = ((lane >> 3) & 1) * 16;

    for (int kc = 0; kc < nkc; kc++) {
        const bool pf = (kc + 2 < nkc);
        float4 f0, f1, f2, f3;
        const int st2 = (kc + 2) % STAGES;
        if (pf) {
            uint32_t sb = sbase + st2 * STAGEB;
            int kof = (kc + 2) * 32;
            cp16(sb + 2 * TILEB + lrow0 * ROWB + lseg * 16,
                 Bh + (size_t)(bn * 128 + lrow0) * K + kof + lseg * 8);
            cp16(sb + 2 * TILEB + lrow1 * ROWB + lseg * 16,
                 Bh + (size_t)(bn * 128 + lrow1) * K + kof + lseg * 8);
            CP_COMMIT();
            const float4* Ap = (const float4*)(A + (size_t)(bm * 128 + ar) * K + kof + asg * 16);
            f0 = Ap[0]; f1 = Ap[1]; f2 = Ap[2]; f3 = Ap[3];
        }

        CP_WAIT1();
        __syncthreads();
        uint32_t st = sbase + (kc % STAGES) * STAGEB;
        uint32_t sah = st, sal = st + TILEB, sbh = st + 2 * TILEB;

        #pragma unroll
        for (int ks = 0; ks < 2; ks++) {
            uint32_t ah[2][4], al[2][4], b[8][2];
            #pragma unroll
            for (int mi = 0; mi < 2; mi++)
                ldsm4(ah[mi][0], ah[mi][1], ah[mi][2], ah[mi][3],
                      sah + (a_row + mi * 16) * ROWB + ks * 32 + a_colb);
            #pragma unroll
            for (int np = 0; np < 4; np++) {
                uint32_t r0, r1, r2, r3;
                ldsm4(r0, r1, r2, r3, sbh + (b_row + np * 16) * ROWB + ks * 32 + b_colb);
                b[np * 2 + 0][0] = r0; b[np * 2 + 0][1] = r1;
                b[np * 2 + 1][0] = r2; b[np * 2 + 1][1] = r3;
            }
            #pragma unroll
            for (int mi = 0; mi < 2; mi++)
                #pragma unroll
                for (int ni = 0; ni < 8; ni++)
                    mma16816(acc[mi][ni], ah[mi], b[ni]);
            #pragma unroll
            for (int mi = 0; mi < 2; mi++)
                ldsm4(al[mi][0], al[mi][1], al[mi][2], al[mi][3],
                      sal + (a_row + mi * 16) * ROWB + ks * 32 + a_colb);
            #pragma unroll
            for (int mi = 0; mi < 2; mi++)
                #pragma unroll
                for (int ni = 0; ni < 8; ni++)
                    mma16816(acc[mi][ni], al[mi], b[ni]);
        }

        if (pf) {
            uint4 H0, L0, H1, L1;
            cvt8(f0, f1, H0, L0);
            cvt8(f2, f3, H1, L1);
            char* arow = smem + st2 * STAGEB + ar * ROWB + asg * 32;
            *(uint4*)(arow)              = H0;
            *(uint4*)(arow + 16)         = H1;
            *(uint4*)(arow + TILEB)      = L0;
            *(uint4*)(arow + TILEB + 16) = L1;
        }
        __syncthreads();
    }

    const int r0 = bm * 128 + wm * 32 + (lane >> 2);
    const int c0 = bn * 128 + wn * 64 + (lane & 3) * 2;
    #pragma unroll
    for (int mi = 0; mi < 2; mi++) {
        #pragma unroll
        for (int ni = 0; ni < 8; ni++) {
            int col = c0 + ni * 8;
            int l = col / D_, k = col - l * D_;
            int row0 = r0 + mi * 16, row1 = row0 + 8;
            __half2 v0 = __floats2half2_rn(acc[mi][ni][0], acc[mi][ni][1]);
            __half2 v1 = __floats2half2_rn(acc[mi][ni][2], acc[mi][ni][3]);
            *(uint32_t*)(wc16 + (size_t)l * G_ * D_ + (size_t)row0 * D_ + k) = *(uint32_t*)&v0;
            *(uint32_t*)(wc16 + (size_t)l * G_ * D_ + (size_t)row1 * D_ + k) = *(uint32_t*)&v1;
        }
    }
}

// ================= weight conversions (fp32 -> fp16) =================
__global__ void k_cvt(const float* __restrict__ x, __half* __restrict__ o, int n) {
    int i = blockIdx.x * blockDim.x + threadIdx.x;
    if (i < n) o[i] = __float2half_rn(x[i]);
}
__global__ void k_cvt_t(const float* __restrict__ w, __half* __restrict__ o,
                        int K, int N) {
    int i = blockIdx.x * blockDim.x + threadIdx.x;
    if (i < K * N) {
        int k = i / N, n = i - k * N;
        o[(size_t)n * K + k] = __float2half_rn(w[i]);
    }
}

// ================= CSR build (by dst, per batch) =================
__global__ void k_zero_i(int* __restrict__ p, int n) {
    int i = blockIdx.x * blockDim.x + threadIdx.x;
    if (i < n) p[i] = 0;
}
__global__ void k_count(const int* __restrict__ edst, int* __restrict__ cnt) {
    int be = blockIdx.x * blockDim.x + threadIdx.x;
    if (be < B_ * E_) {
        int b = be / E_;
        atomicAdd(&cnt[b * N_ + edst[be]], 1);
    }
}
__global__ void k_prefix(const int* __restrict__ cnt, int* __restrict__ off,
                         int* __restrict__ pos) {
    __shared__ int s[N_];
    int b = blockIdx.x, n = threadIdx.x;
    int v = cnt[b * N_ + n];
    s[n] = v;
    __syncthreads();
    #pragma unroll
    for (int d = 1; d < N_; d <<= 1) {
        int t = (n >= d) ? s[n - d] : 0;
        __syncthreads();
        s[n] += t;
        __syncthreads();
    }
    off[b * (N_ + 1) + n + 1] = s[n];
    if (n == 0) off[b * (N_ + 1)] = 0;
    pos[b * N_ + n] = s[n] - v;
}
__global__ void k_fill(const int* __restrict__ esrc, const int* __restrict__ edst,
                       const float* __restrict__ ew, int* __restrict__ pos,
                       int* __restrict__ src_s, float* __restrict__ w_s) {
    int be = blockIdx.x * blockDim.x + threadIdx.x;
    if (be < B_ * E_) {
        int b = be / E_;
        int p = atomicAdd(&pos[b * N_ + edst[be]], 1);
        src_s[b * E_ + p] = esrc[be];
        w_s[b * E_ + p] = ew[be];
    }
}
__global__ void k_gather(const int* __restrict__ off, const int* __restrict__ src_s,
                         const float* __restrict__ w_s, const float* __restrict__ h,
                         float* __restrict__ q) {
    int bn = blockIdx.x;
    int b = bn >> 9, n = bn & 511;
    int o0 = off[b * (N_ + 1) + n], o1 = off[b * (N_ + 1) + n + 1];
    int d = threadIdx.x;
    float4 acc = make_float4(0.f, 0.f, 0.f, 0.f);
    const float* hb = h + (size_t)b * N_ * D_;
    for (int e = o0; e < o1; e++) {
        int s = src_s[b * E_ + e];
        float w = w_s[b * E_ + e];
        float4 v = ((const float4*)(hb + (size_t)s * D_))[d];
        acc.x += v.x * w; acc.y += v.y * w; acc.z += v.z * w; acc.w += v.w * w;
    }
    ((float4*)(q + (size_t)bn * D_))[d] = acc;
}

// ================= embed =================
__global__ void k_embed(const int* __restrict__ types, const int* __restrict__ tok,
                        const int* __restrict__ lens, const float* __restrict__ table,
                        const float* __restrict__ emb, float* __restrict__ fused) {
    int bn = blockIdx.x;
    int b = bn >> 9, n = bn & 511;
    int base = b * T_ + n * TPN_;
    int t0 = tok[base], t1 = tok[base + 1], t2 = tok[base + 2], t3 = tok[base + 3];
    float inv = 1.0f / (float)lens[bn];
    float* o = fused + (size_t)bn * F_;
    int d = threadIdx.x;
    if (d < TD_ / 4)
        ((float4*)o)[d] = ((const float4*)(table + (size_t)types[bn] * TD_))[d];
    float4 e0 = ((const float4*)(emb + (size_t)t0 * D_))[d];
    float4 e1 = ((const float4*)(emb + (size_t)t1 * D_))[d];
    float4 e2 = ((const float4*)(emb + (size_t)t2 * D_))[d];
    float4 e3 = ((const float4*)(emb + (size_t)t3 * D_))[d];
    float4 s;
    s.x = (e0.x + e1.x + e2.x + e3.x) * inv;
    s.y = (e0.y + e1.y + e2.y + e3.y) * inv;
    s.z = (e0.z + e1.z + e2.z + e3.z) * inv;
    s.w = (e0.w + e1.w + e2.w + e3.w) * inv;
    ((float4*)(o + TD_))[d] = s;
}

// ================= GRU + output =================
__global__ void k_gru(const float* __restrict__ gi, const float* __restrict__ gh,
                      float* __restrict__ h) {
    int row = blockIdx.x;
    const float* gip = gi + (size_t)row * G_;
    const float* ghp = gh + (size_t)row * G_;
    float* hp = h + (size_t)row * D_;
    #pragma unroll
    for (int d = threadIdx.x; d < D_; d += 256) {
        float ir = gip[d], iz = gip[D_ + d], in = gip[2 * D_ + d];
        float hr = ghp[d], hz = ghp[D_ + d], hn = ghp[2 * D_ + d];
        float r = 1.0f / (1.0f + expf(-(ir + hr)));
        float z = 1.0f / (1.0f + expf(-(iz + hz)));
        float n = tanhf(in + r * hn);
        hp[d] = (1.0f - z) * n + z * hp[d];
    }
}

__global__ void k_out(const float* __restrict__ h, const int* __restrict__ keep,
                      float* __restrict__ out) {
    int bw = blockIdx.x;
    int b = bw >> 9;
    int wn = bw & 511;
    int kp = keep[b]; if (kp > 512) kp = 512;
    bool valid = wn < kp;
    const float4* hp = (const float4*)(h + (size_t)bw * D_);
    float4* op = (float4*)(out + (size_t)bw * D_);
    int d = threadIdx.x;
    float4 v = valid ? hp[d] : make_float4(0.f, 0.f, 0.f, 0.f);
    op[d] = v;
}

// ================= launch =================
extern "C" void kernel_launch(void* const* d_in, const int* in_sizes, int n_in,
                              void* d_out, int out_size) {
    const int*   node_types = (const int*)d_in[0];
    const int*   tok_ids    = (const int*)d_in[1];
    const int*   seg_ids    = (const int*)d_in[2]; (void)seg_ids;
    const int*   tok_lens   = (const int*)d_in[3];
    const int*   gnode_lens = (const int*)d_in[4];
    const int*   esrc       = (const int*)d_in[5];
    const int*   edst       = (const int*)d_in[6];
    const float* ew         = (const float*)d_in[7];
    const float* type_table = (const float*)d_in[8];
    const float* word_emb   = (const float*)d_in[9];
    const float* fusion_w   = (const float*)d_in[10];
    const float* fusion_b   = (const float*)d_in[11];
    const float* ggnn_w     = (const float*)d_in[12];
    const float* w_ih       = (const float*)d_in[13];
    const float* w_hh       = (const float*)d_in[14];
    const float* b_ih       = (const float*)d_in[15];
    const float* b_hh       = (const float*)d_in[16];
    float* out = (float*)d_out;

    cudaFuncSetAttribute(bmma,    cudaFuncAttributeMaxDynamicSharedMemorySize, SMEM_SZ);
    cudaFuncSetAttribute(bmma_wc, cudaFuncAttributeMaxDynamicSharedMemorySize, SMEM_SZ);

    static cudaStream_t s1 = nullptr;
    static cudaEvent_t eH = nullptr, eG = nullptr, eW = nullptr;
    if (!s1) {
        cudaStreamCreateWithFlags(&s1, cudaStreamNonBlocking);
        cudaEventCreateWithFlags(&eH, cudaEventDisableTiming);
        cudaEventCreateWithFlags(&eG, cudaEventDisableTiming);
        cudaEventCreateWithFlags(&eW, cudaEventDisableTiming);
    }

    float *fused, *h, *q, *gi, *gh;
    cudaGetSymbolAddress((void**)&fused, g_fused);
    cudaGetSymbolAddress((void**)&h,     g_h);
    cudaGetSymbolAddress((void**)&q,     g_q);
    cudaGetSymbolAddress((void**)&gi,    g_gi);
    cudaGetSymbolAddress((void**)&gh,    g_gh);

    __half *fw, *gwnt, *hh, *wc16;
    cudaGetSymbolAddress((void**)&fw,   s_fw);
    cudaGetSymbolAddress((void**)&gwnt, s_gwnt);
    cudaGetSymbolAddress((void**)&hh,   s_hh);
    cudaGetSymbolAddress((void**)&wc16, s_wc16);

    int *cnt, *off, *pos, *src_s; float *w_s;
    cudaGetSymbolAddress((void**)&cnt,   g_cnt);
    cudaGetSymbolAddress((void**)&off,   g_off);
    cudaGetSymbolAddress((void**)&pos,   g_pos);
    cudaGetSymbolAddress((void**)&src_s, g_src_s);
    cudaGetSymbolAddress((void**)&w_s,   g_w_s);

    // ---- fork: side stream builds Wc (ONE GEMM, direct fp16 epi), hh, CSR ----
    cudaEventRecord(eH, 0);
    cudaStreamWaitEvent(s1, eH, 0);
    k_cvt<<<(L_ * D_ * D_ + 255) / 256, 256, 0, s1>>>(ggnn_w, gwnt, L_ * D_ * D_);
    bmma_wc<<<dim3(LD_ / 128, G_ / 128), 256, SMEM_SZ, s1>>>(
        w_ih, gwnt, wc16, LD_, D_);
    k_cvt<<<(G_ * D_ + 255) / 256, 256, 0, s1>>>(w_hh, hh, G_ * D_);
    k_zero_i<<<(B_ * N_ + 255) / 256, 256, 0, s1>>>(cnt, B_ * N_);
    k_count<<<(B_ * E_ + 255) / 256, 256, 0, s1>>>(edst, cnt);
    k_prefix<<<B_, N_, 0, s1>>>(cnt, off, pos);
    k_fill<<<(B_ * E_ + 255) / 256, 256, 0, s1>>>(esrc, edst, ew, pos, src_s, w_s);
    cudaEventRecord(eW, s1);

    // ---- main stream: fw cvt, embed, fusion GEMM ----
    k_cvt_t<<<(F_ * D_ + 255) / 256, 256>>>(fusion_w, fw, F_, D_);
    k_embed<<<M_, 192>>>(node_types, tok_ids, tok_lens, type_table, word_emb, fused);
    bmma<<<dim3(D_ / 128, M_ / 128), 256, SMEM_SZ>>>(fused, fw, fusion_b, h, D_, F_);

    cudaStreamWaitEvent(0, eW, 0);

    for (int l = 0; l < L_; ++l) {
        // fork gh onto side stream (depends only on h)
        cudaEventRecord(eH, 0);
        cudaStreamWaitEvent(s1, eH, 0);
        bmma<<<dim3(G_ / 128, M_ / 128), 256, SMEM_SZ, s1>>>(h, hh, b_hh, gh, G_, D_);
        cudaEventRecord(eG, s1);

        // main chain: q = gather(h) -> gi = q @ Wc[l] + b_ih
        k_gather<<<M_, 192>>>(off, src_s, w_s, h, q);
        bmma<<<dim3(G_ / 128, M_ / 128), 256, SMEM_SZ>>>(
            q, wc16 + (size_t)l * G_ * D_, b_ih, gi, G_, D_);

        cudaStreamWaitEvent(0, eG, 0);
        k_gru<<<M_, 256>>>(gi, gh, h);
    }

    k_out<<<M_, 192>>>(h, gnode_lens, out);
}

// round 16
// speedup vs baseline: 1.0510x; 1.0510x over previous
#include <cuda_runtime.h>
#include <cuda_fp16.h>
#include <cstdint>
#include <cstddef>

#define B_ 8
#define N_ 512
#define T_ 2048
#define E_ 4096
#define D_ 768
#define TD_ 128
#define L_ 4
#define F_ (TD_ + D_)   /* 896 */
#define G_ (3 * D_)     /* 2304 */
#define M_ (B_ * N_)    /* 4096 */
#define TPN_ (T_ / N_)  /* 4 tokens per node */
#define LD_ (L_ * D_)   /* 3072 */

// ---------------- fp32 scratch ----------------
__device__ float g_fused[M_ * F_];
__device__ float g_h    [M_ * D_];
__device__ float g_q    [M_ * D_];      // q = gather(h)
__device__ float g_gi   [M_ * G_];
__device__ float g_gh   [M_ * G_];

// ---------------- CSR scratch ----------------
__device__ int   g_cnt  [B_ * N_];
__device__ int   g_off  [B_ * (N_ + 1)];
__device__ int   g_pos  [B_ * N_];
__device__ int   g_src_s[B_ * E_];
__device__ float g_w_s  [B_ * E_];

// ---------------- fp16 weights (K-major) ----------------
__device__ __half s_fw  [D_ * F_];        // fusion_w^T  [768][896]
__device__ __half s_gwnt[L_ * D_ * D_];   // ggnn_w plain fp16 (= [3072][768] B op)
__device__ __half s_hh  [G_ * D_];        // w_hh [2304][768]
__device__ __half s_wc16[L_ * G_ * D_];   // Wc^T fp16 [l][2304][768]

// ================= helpers =================
__device__ __forceinline__ uint32_t smem_u32(const void* p) {
    uint32_t a;
    asm("{ .reg .u64 t; cvta.to.shared.u64 t, %1; cvt.u32.u64 %0, t; }" : "=r"(a) : "l"(p));
    return a;
}
__device__ __forceinline__ void cp16(uint32_t saddr, const void* g) {
    asm volatile("cp.async.cg.shared.global [%0], [%1], 16;" :: "r"(saddr), "l"(g) : "memory");
}
#define CP_COMMIT() asm volatile("cp.async.commit_group;" ::: "memory")
#define CP_WAIT0()  asm volatile("cp.async.wait_group 0;" ::: "memory")

__device__ __forceinline__ void ldsm4(uint32_t& r0, uint32_t& r1, uint32_t& r2,
                                      uint32_t& r3, uint32_t a) {
    asm volatile("ldmatrix.sync.aligned.m8n8.x4.shared.b16 {%0,%1,%2,%3}, [%4];"
                 : "=r"(r0), "=r"(r1), "=r"(r2), "=r"(r3) : "r"(a));
}
__device__ __forceinline__ void mma16816(float* d, const uint32_t* a, const uint32_t* b) {
    asm volatile(
        "mma.sync.aligned.m16n8k16.row.col.f32.f16.f16.f32 "
        "{%0,%1,%2,%3}, {%4,%5,%6,%7}, {%8,%9}, {%0,%1,%2,%3};"
        : "+f"(d[0]), "+f"(d[1]), "+f"(d[2]), "+f"(d[3])
        : "r"(a[0]), "r"(a[1]), "r"(a[2]), "r"(a[3]), "r"(b[0]), "r"(b[1]));
}

// 8 fp32 -> 4x half2 hi + 4x half2 lo (packed)
__device__ __forceinline__ void cvt8(float4 f0, float4 f1, uint4& H, uint4& Lo) {
    __half2 h0 = __floats2half2_rn(f0.x, f0.y);
    __half2 h1 = __floats2half2_rn(f0.z, f0.w);
    __half2 h2 = __floats2half2_rn(f1.x, f1.y);
    __half2 h3 = __floats2half2_rn(f1.z, f1.w);
    __half2 l0 = __floats2half2_rn(f0.x - __half2float(h0.x), f0.y - __half2float(h0.y));
    __half2 l1 = __floats2half2_rn(f0.z - __half2float(h1.x), f0.w - __half2float(h1.y));
    __half2 l2 = __floats2half2_rn(f1.x - __half2float(h2.x), f1.y - __half2float(h2.y));
    __half2 l3 = __floats2half2_rn(f1.z - __half2float(h3.x), f1.w - __half2float(h3.y));
    H.x  = *(uint32_t*)&h0; H.y  = *(uint32_t*)&h1; H.z  = *(uint32_t*)&h2; H.w  = *(uint32_t*)&h3;
    Lo.x = *(uint32_t*)&l0; Lo.y = *(uint32_t*)&l1; Lo.z = *(uint32_t*)&l2; Lo.w = *(uint32_t*)&l3;
}

// smem tile: 128 rows x 32 halves (64B) + 16B pad -> 80B row stride
#define ROWB    80
#define TILEB   (128 * ROWB)          /* 10240 */
#define STAGEB  (3 * TILEB)           /* Ahi, Alo, B = 30720 */
#define STAGES  2
#define SMEM_SZ (STAGES * STAGEB)     /* 61440 -> 2 CTAs/SM */

// ======== bmma: fp32-A 2-term fp16 GEMM, fp32 C + bias (R12/R14-proven) ======
__global__ void __launch_bounds__(256, 2) bmma(
    const float* __restrict__ A, const __half* __restrict__ Bh,
    const float* __restrict__ bias, float* __restrict__ C, int N, int K)
{
    extern __shared__ char smem[];
    const uint32_t sbase = smem_u32(smem);
    const int tid = threadIdx.x;
    const int wid = tid >> 5, lane = tid & 31;
    const int wm = wid & 3, wn = wid >> 2;
    const int bn = blockIdx.x, bm = blockIdx.y;
    const int nkc = K >> 5;

    const int lrow0 = tid >> 2;
    const int lrow1 = 64 + (tid >> 2);
    const int lseg  = tid & 3;
    const int ar = tid >> 1;
    const int asg = tid & 1;

    {   // prologue stage 0
        cp16(sbase + 2 * TILEB + lrow0 * ROWB + lseg * 16,
             Bh + (size_t)(bn * 128 + lrow0) * K + lseg * 8);
        cp16(sbase + 2 * TILEB + lrow1 * ROWB + lseg * 16,
             Bh + (size_t)(bn * 128 + lrow1) * K + lseg * 8);
        CP_COMMIT();
        const float4* Ap = (const float4*)(A + (size_t)(bm * 128 + ar) * K + asg * 16);
        float4 f0 = Ap[0], f1 = Ap[1], f2 = Ap[2], f3 = Ap[3];
        uint4 H0, L0, H1, L1;
        cvt8(f0, f1, H0, L0);
        cvt8(f2, f3, H1, L1);
        char* arow = smem + ar * ROWB + asg * 32;
        *(uint4*)(arow)              = H0;
        *(uint4*)(arow + 16)         = H1;
        *(uint4*)(arow + TILEB)      = L0;
        *(uint4*)(arow + TILEB + 16) = L1;
    }

    float acc[2][8][4];
    #pragma unroll
    for (int i = 0; i < 2; i++)
        #pragma unroll
        for (int j = 0; j < 8; j++)
            #pragma unroll
            for (int q = 0; q < 4; q++) acc[i][j][q] = 0.f;

    const int a_row  = wm * 32 + (lane & 15);
    const int a_colb = (lane >> 4) * 16;
    const int b_row  = wn * 64 + (lane & 7) + ((lane >> 4) << 3);
    const int b_colb = ((lane >> 3) & 1) * 16;

    for (int kc = 0; kc < nkc; kc++) {
        CP_WAIT0();
        __syncthreads();

        const bool pf = (kc + 1 < nkc);
        float4 f0, f1, f2, f3;
        const int stn = (kc + 1) & 1;
        if (pf) {
            uint32_t sb = sbase + stn * STAGEB;
            int kof = (kc + 1) * 32;
            cp16(sb + 2 * TILEB + lrow0 * ROWB + lseg * 16,
                 Bh + (size_t)(bn * 128 + lrow0) * K + kof + lseg * 8);
            cp16(sb + 2 * TILEB + lrow1 * ROWB + lseg * 16,
                 Bh + (size_t)(bn * 128 + lrow1) * K + kof + lseg * 8);
            CP_COMMIT();
            const float4* Ap = (const float4*)(A + (size_t)(bm * 128 + ar) * K + kof + asg * 16);
            f0 = Ap[0]; f1 = Ap[1]; f2 = Ap[2]; f3 = Ap[3];
        }

        uint32_t st = sbase + (kc & 1) * STAGEB;
        uint32_t sah = st, sal = st + TILEB, sbh = st + 2 * TILEB;

        #pragma unroll
        for (int ks = 0; ks < 2; ks++) {
            uint32_t ah[2][4], al[2][4], b[8][2];
            #pragma unroll
            for (int mi = 0; mi < 2; mi++)
                ldsm4(ah[mi][0], ah[mi][1], ah[mi][2], ah[mi][3],
                      sah + (a_row + mi * 16) * ROWB + ks * 32 + a_colb);
            #pragma unroll
            for (int np = 0; np < 4; np++) {
                uint32_t r0, r1, r2, r3;
                ldsm4(r0, r1, r2, r3, sbh + (b_row + np * 16) * ROWB + ks * 32 + b_colb);
                b[np * 2 + 0][0] = r0; b[np * 2 + 0][1] = r1;
                b[np * 2 + 1][0] = r2; b[np * 2 + 1][1] = r3;
            }
            #pragma unroll
            for (int mi = 0; mi < 2; mi++)
                #pragma unroll
                for (int ni = 0; ni < 8; ni++)
                    mma16816(acc[mi][ni], ah[mi], b[ni]);
            #pragma unroll
            for (int mi = 0; mi < 2; mi++)
                ldsm4(al[mi][0], al[mi][1], al[mi][2], al[mi][3],
                      sal + (a_row + mi * 16) * ROWB + ks * 32 + a_colb);
            #pragma unroll
            for (int mi = 0; mi < 2; mi++)
                #pragma unroll
                for (int ni = 0; ni < 8; ni++)
                    mma16816(acc[mi][ni], al[mi], b[ni]);
        }

        if (pf) {
            uint4 H0, L0, H1, L1;
            cvt8(f0, f1, H0, L0);
            cvt8(f2, f3, H1, L1);
            char* arow = smem + stn * STAGEB + ar * ROWB + asg * 32;
            *(uint4*)(arow)              = H0;
            *(uint4*)(arow + 16)         = H1;
            *(uint4*)(arow + TILEB)      = L0;
            *(uint4*)(arow + TILEB + 16) = L1;
        }
    }

    const int r0 = bm * 128 + wm * 32 + (lane >> 2);
    const int c0 = bn * 128 + wn * 64 + (lane & 3) * 2;
    #pragma unroll
    for (int mi = 0; mi < 2; mi++) {
        #pragma unroll
        for (int ni = 0; ni < 8; ni++) {
            int col = c0 + ni * 8;
            float bx = 0.f, by = 0.f;
            if (bias) { bx = bias[col]; by = bias[col + 1]; }
            *(float2*)(C + (size_t)(r0 + mi * 16) * N + col) =
                make_float2(acc[mi][ni][0] + bx, acc[mi][ni][1] + by);
            *(float2*)(C + (size_t)(r0 + mi * 16 + 8) * N + col) =
                make_float2(acc[mi][ni][2] + bx, acc[mi][ni][3] + by);
        }
    }
}

// ======== bmma_wc: same mainloop, direct fp16 re-strided epilogue ========
__global__ void __launch_bounds__(256, 2) bmma_wc(
    const float* __restrict__ A, const __half* __restrict__ Bh,
    __half* __restrict__ wc16, int N, int K)
{
    extern __shared__ char smem[];
    const uint32_t sbase = smem_u32(smem);
    const int tid = threadIdx.x;
    const int wid = tid >> 5, lane = tid & 31;
    const int wm = wid & 3, wn = wid >> 2;
    const int bn = blockIdx.x, bm = blockIdx.y;
    const int nkc = K >> 5;

    const int lrow0 = tid >> 2;
    const int lrow1 = 64 + (tid >> 2);
    const int lseg  = tid & 3;
    const int ar = tid >> 1;
    const int asg = tid & 1;

    {   // prologue stage 0
        cp16(sbase + 2 * TILEB + lrow0 * ROWB + lseg * 16,
             Bh + (size_t)(bn * 128 + lrow0) * K + lseg * 8);
        cp16(sbase + 2 * TILEB + lrow1 * ROWB + lseg * 16,
             Bh + (size_t)(bn * 128 + lrow1) * K + lseg * 8);
        CP_COMMIT();
        const float4* Ap = (const float4*)(A + (size_t)(bm * 128 + ar) * K + asg * 16);
        float4 f0 = Ap[0], f1 = Ap[1], f2 = Ap[2], f3 = Ap[3];
        uint4 H0, L0, H1, L1;
        cvt8(f0, f1, H0, L0);
        cvt8(f2, f3, H1, L1);
        char* arow = smem + ar * ROWB + asg * 32;
        *(uint4*)(arow)              = H0;
        *(uint4*)(arow + 16)         = H1;
        *(uint4*)(arow + TILEB)      = L0;
        *(uint4*)(arow + TILEB + 16) = L1;
    }

    float acc[2][8][4];
    #pragma unroll
    for (int i = 0; i < 2; i++)
        #pragma unroll
        for (int j = 0; j < 8; j++)
            #pragma unroll
            for (int q = 0; q < 4; q++) acc[i][j][q] = 0.f;

    const int a_row  = wm * 32 + (lane & 15);
    const int a_colb = (lane >> 4) * 16;
    const int b_row  = wn * 64 + (lane & 7) + ((lane >> 4) << 3);
    const int b_colb = ((lane >> 3) & 1) * 16;

    for (int kc = 0; kc < nkc; kc++) {
        CP_WAIT0();
        __syncthreads();

        const bool pf = (kc + 1 < nkc);
        float4 f0, f1, f2, f3;
        const int stn = (kc + 1) & 1;
        if (pf) {
            uint32_t sb = sbase + stn * STAGEB;
            int kof = (kc + 1) * 32;
            cp16(sb + 2 * TILEB + lrow0 * ROWB + lseg * 16,
                 Bh + (size_t)(bn * 128 + lrow0) * K + kof + lseg * 8);
            cp16(sb + 2 * TILEB + lrow1 * ROWB + lseg * 16,
                 Bh + (size_t)(bn * 128 + lrow1) * K + kof + lseg * 8);
            CP_COMMIT();
            const float4* Ap = (const float4*)(A + (size_t)(bm * 128 + ar) * K + kof + asg * 16);
            f0 = Ap[0]; f1 = Ap[1]; f2 = Ap[2]; f3 = Ap[3];
        }

        uint32_t st = sbase + (kc & 1) * STAGEB;
        uint32_t sah = st, sal = st + TILEB, sbh = st + 2 * TILEB;

        #pragma unroll
        for (int ks = 0; ks < 2; ks++) {
            uint32_t ah[2][4], al[2][4], b[8][2];
            #pragma unroll
            for (int mi = 0; mi < 2; mi++)
                ldsm4(ah[mi][0], ah[mi][1], ah[mi][2], ah[mi][3],
                      sah + (a_row + mi * 16) * ROWB + ks * 32 + a_colb);
            #pragma unroll
            for (int np = 0; np < 4; np++) {
                uint32_t r0, r1, r2, r3;
                ldsm4(r0, r1, r2, r3, sbh + (b_row + np * 16) * ROWB + ks * 32 + b_colb);
                b[np * 2 + 0][0] = r0; b[np * 2 + 0][1] = r1;
                b[np * 2 + 1][0] = r2; b[np * 2 + 1][1] = r3;
            }
            #pragma unroll
            for (int mi = 0; mi < 2; mi++)
                #pragma unroll
                for (int ni = 0; ni < 8; ni++)
                    mma16816(acc[mi][ni], ah[mi], b[ni]);
            #pragma unroll
            for (int mi = 0; mi < 2; mi++)
                ldsm4(al[mi][0], al[mi][1], al[mi][2], al[mi][3],
                      sal + (a_row + mi * 16) * ROWB + ks * 32 + a_colb);
            #pragma unroll
            for (int mi = 0; mi < 2; mi++)
                #pragma unroll
                for (int ni = 0; ni < 8; ni++)
                    mma16816(acc[mi][ni], al[mi], b[ni]);
        }

        if (pf) {
            uint4 H0, L0, H1, L1;
            cvt8(f0, f1, H0, L0);
            cvt8(f2, f3, H1, L1);
            char* arow = smem + stn * STAGEB + ar * ROWB + asg * 32;
            *(uint4*)(arow)              = H0;
            *(uint4*)(arow + 16)         = H1;
            *(uint4*)(arow + TILEB)      = L0;
            *(uint4*)(arow + TILEB + 16) = L1;
        }
    }

    // epilogue: col in [0, 3072); l = col/768, k = col%768 -> wc16[l][row][k]
    const int r0 = bm * 128 + wm * 32 + (lane >> 2);
    const int c0 = bn * 128 + wn * 64 + (lane & 3) * 2;
    #pragma unroll
    for (int mi = 0; mi < 2; mi++) {
        #pragma unroll
        for (int ni = 0; ni < 8; ni++) {
            int col = c0 + ni * 8;
            int l = col / D_, k = col - l * D_;
            int row0 = r0 + mi * 16, row1 = row0 + 8;
            __half2 v0 = __floats2half2_rn(acc[mi][ni][0], acc[mi][ni][1]);
            __half2 v1 = __floats2half2_rn(acc[mi][ni][2], acc[mi][ni][3]);
            *(uint32_t*)(wc16 + (size_t)l * G_ * D_ + (size_t)row0 * D_ + k) = *(uint32_t*)&v0;
            *(uint32_t*)(wc16 + (size_t)l * G_ * D_ + (size_t)row1 * D_ + k) = *(uint32_t*)&v1;
        }
    }
}

// ================= weight conversions (fp32 -> fp16) =================
__global__ void k_cvt(const float* __restrict__ x, __half* __restrict__ o, int n) {
    int i = blockIdx.x * blockDim.x + threadIdx.x;
    if (i < n) o[i] = __float2half_rn(x[i]);
}
__global__ void k_cvt_t(const float* __restrict__ w, __half* __restrict__ o,
                        int K, int N) {
    int i = blockIdx.x * blockDim.x + threadIdx.x;
    if (i < K * N) {
        int k = i / N, n = i - k * N;
        o[(size_t)n * K + k] = __float2half_rn(w[i]);
    }
}

// ================= CSR build (by dst, per batch) =================
__global__ void k_zero_i(int* __restrict__ p, int n) {
    int i = blockIdx.x * blockDim.x + threadIdx.x;
    if (i < n) p[i] = 0;
}
__global__ void k_count(const int* __restrict__ edst, int* __restrict__ cnt) {
    int be = blockIdx.x * blockDim.x + threadIdx.x;
    if (be < B_ * E_) {
        int b = be / E_;
        atomicAdd(&cnt[b * N_ + edst[be]], 1);
    }
}
__global__ void k_prefix(const int* __restrict__ cnt, int* __restrict__ off,
                         int* __restrict__ pos) {
    __shared__ int s[N_];
    int b = blockIdx.x, n = threadIdx.x;
    int v = cnt[b * N_ + n];
    s[n] = v;
    __syncthreads();
    #pragma unroll
    for (int d = 1; d < N_; d <<= 1) {
        int t = (n >= d) ? s[n - d] : 0;
        __syncthreads();
        s[n] += t;
        __syncthreads();
    }
    off[b * (N_ + 1) + n + 1] = s[n];
    if (n == 0) off[b * (N_ + 1)] = 0;
    pos[b * N_ + n] = s[n] - v;
}
__global__ void k_fill(const int* __restrict__ esrc, const int* __restrict__ edst,
                       const float* __restrict__ ew, int* __restrict__ pos,
                       int* __restrict__ src_s, float* __restrict__ w_s) {
    int be = blockIdx.x * blockDim.x + threadIdx.x;
    if (be < B_ * E_) {
        int b = be / E_;
        int p = atomicAdd(&pos[b * N_ + edst[be]], 1);
        src_s[b * E_ + p] = esrc[be];
        w_s[b * E_ + p] = ew[be];
    }
}
// q[b,n,:] = sum over incoming edges w * h[b,src,:]  (768-wide)
__global__ void k_gather(const int* __restrict__ off, const int* __restrict__ src_s,
                         const float* __restrict__ w_s, const float* __restrict__ h,
                         float* __restrict__ q) {
    int bn = blockIdx.x;
    int b = bn >> 9, n = bn & 511;
    int o0 = off[b * (N_ + 1) + n], o1 = off[b * (N_ + 1) + n + 1];
    int d = threadIdx.x;               // 192
    float4 acc = make_float4(0.f, 0.f, 0.f, 0.f);
    const float* hb = h + (size_t)b * N_ * D_;
    for (int e = o0; e < o1; e++) {
        int s = src_s[b * E_ + e];
        float w = w_s[b * E_ + e];
        float4 v = ((const float4*)(hb + (size_t)s * D_))[d];
        acc.x += v.x * w; acc.y += v.y * w; acc.z += v.z * w; acc.w += v.w * w;
    }
    ((float4*)(q + (size_t)bn * D_))[d] = acc;
}

// ================= embed =================
__global__ void k_embed(const int* __restrict__ types, const int* __restrict__ tok,
                        const int* __restrict__ lens, const float* __restrict__ table,
                        const float* __restrict__ emb, float* __restrict__ fused) {
    int bn = blockIdx.x;
    int b = bn >> 9, n = bn & 511;
    int base = b * T_ + n * TPN_;
    int t0 = tok[base], t1 = tok[base + 1], t2 = tok[base + 2], t3 = tok[base + 3];
    float inv = 1.0f / (float)lens[bn];
    float* o = fused + (size_t)bn * F_;
    int d = threadIdx.x;
    if (d < TD_ / 4)
        ((float4*)o)[d] = ((const float4*)(table + (size_t)types[bn] * TD_))[d];
    float4 e0 = ((const float4*)(emb + (size_t)t0 * D_))[d];
    float4 e1 = ((const float4*)(emb + (size_t)t1 * D_))[d];
    float4 e2 = ((const float4*)(emb + (size_t)t2 * D_))[d];
    float4 e3 = ((const float4*)(emb + (size_t)t3 * D_))[d];
    float4 s;
    s.x = (e0.x + e1.x + e2.x + e3.x) * inv;
    s.y = (e0.y + e1.y + e2.y + e3.y) * inv;
    s.z = (e0.z + e1.z + e2.z + e3.z) * inv;
    s.w = (e0.w + e1.w + e2.w + e3.w) * inv;
    ((float4*)(o + TD_))[d] = s;
}

// ================= GRU (intermediate layers) =================
__global__ void k_gru(const float* __restrict__ gi, const float* __restrict__ gh,
                      float* __restrict__ h) {
    int row = blockIdx.x;
    const float* gip = gi + (size_t)row * G_;
    const float* ghp = gh + (size_t)row * G_;
    float* hp = h + (size_t)row * D_;
    #pragma unroll
    for (int d = threadIdx.x; d < D_; d += 256) {
        float ir = gip[d], iz = gip[D_ + d], in = gip[2 * D_ + d];
        float hr = ghp[d], hz = ghp[D_ + d], hn = ghp[2 * D_ + d];
        float r = 1.0f / (1.0f + expf(-(ir + hr)));
        float z = 1.0f / (1.0f + expf(-(iz + hz)));
        float n = tanhf(in + r * hn);
        hp[d] = (1.0f - z) * n + z * hp[d];
    }
}

// ================= GRU final layer: masked write straight to out =============
__global__ void k_gru_out(const float* __restrict__ gi, const float* __restrict__ gh,
                          const float* __restrict__ h, const int* __restrict__ keep,
                          float* __restrict__ out) {
    int row = blockIdx.x;              // == b*512 + w
    int b = row >> 9;
    int wn = row & 511;
    int kp = keep[b]; if (kp > 512) kp = 512;
    bool valid = wn < kp;
    const float* gip = gi + (size_t)row * G_;
    const float* ghp = gh + (size_t)row * G_;
    const float* hp = h + (size_t)row * D_;
    float* op = out + (size_t)row * D_;
    #pragma unroll
    for (int d = threadIdx.x; d < D_; d += 256) {
        float ir = gip[d], iz = gip[D_ + d], in = gip[2 * D_ + d];
        float hr = ghp[d], hz = ghp[D_ + d], hn = ghp[2 * D_ + d];
        float r = 1.0f / (1.0f + expf(-(ir + hr)));
        float z = 1.0f / (1.0f + expf(-(iz + hz)));
        float n = tanhf(in + r * hn);
        float v = (1.0f - z) * n + z * hp[d];
        op[d] = valid ? v : 0.0f;
    }
}

// ================= launch =================
extern "C" void kernel_launch(void* const* d_in, const int* in_sizes, int n_in,
                              void* d_out, int out_size) {
    const int*   node_types = (const int*)d_in[0];
    const int*   tok_ids    = (const int*)d_in[1];
    const int*   seg_ids    = (const int*)d_in[2]; (void)seg_ids;
    const int*   tok_lens   = (const int*)d_in[3];
    const int*   gnode_lens = (const int*)d_in[4];
    const int*   esrc       = (const int*)d_in[5];
    const int*   edst       = (const int*)d_in[6];
    const float* ew         = (const float*)d_in[7];
    const float* type_table = (const float*)d_in[8];
    const float* word_emb   = (const float*)d_in[9];
    const float* fusion_w   = (const float*)d_in[10];
    const float* fusion_b   = (const float*)d_in[11];
    const float* ggnn_w     = (const float*)d_in[12];
    const float* w_ih       = (const float*)d_in[13];
    const float* w_hh       = (const float*)d_in[14];
    const float* b_ih       = (const float*)d_in[15];
    const float* b_hh       = (const float*)d_in[16];
    float* out = (float*)d_out;

    cudaFuncSetAttribute(bmma,    cudaFuncAttributeMaxDynamicSharedMemorySize, SMEM_SZ);
    cudaFuncSetAttribute(bmma_wc, cudaFuncAttributeMaxDynamicSharedMemorySize, SMEM_SZ);

    static cudaStream_t s1 = nullptr;
    static cudaEvent_t eH = nullptr, eG = nullptr, eW = nullptr;
    if (!s1) {
        cudaStreamCreateWithFlags(&s1, cudaStreamNonBlocking);
        cudaEventCreateWithFlags(&eH, cudaEventDisableTiming);
        cudaEventCreateWithFlags(&eG, cudaEventDisableTiming);
        cudaEventCreateWithFlags(&eW, cudaEventDisableTiming);
    }

    float *fused, *h, *q, *gi, *gh;
    cudaGetSymbolAddress((void**)&fused, g_fused);
    cudaGetSymbolAddress((void**)&h,     g_h);
    cudaGetSymbolAddress((void**)&q,     g_q);
    cudaGetSymbolAddress((void**)&gi,    g_gi);
    cudaGetSymbolAddress((void**)&gh,    g_gh);

    __half *fw, *gwnt, *hh, *wc16;
    cudaGetSymbolAddress((void**)&fw,   s_fw);
    cudaGetSymbolAddress((void**)&gwnt, s_gwnt);
    cudaGetSymbolAddress((void**)&hh,   s_hh);
    cudaGetSymbolAddress((void**)&wc16, s_wc16);

    int *cnt, *off, *pos, *src_s; float *w_s;
    cudaGetSymbolAddress((void**)&cnt,   g_cnt);
    cudaGetSymbolAddress((void**)&off,   g_off);
    cudaGetSymbolAddress((void**)&pos,   g_pos);
    cudaGetSymbolAddress((void**)&src_s, g_src_s);
    cudaGetSymbolAddress((void**)&w_s,   g_w_s);

    // ---- fork: side stream builds Wc (ONE GEMM, direct fp16 epi), hh, CSR ----
    cudaEventRecord(eH, 0);
    cudaStreamWaitEvent(s1, eH, 0);
    k_cvt<<<(L_ * D_ * D_ + 255) / 256, 256, 0, s1>>>(ggnn_w, gwnt, L_ * D_ * D_);
    bmma_wc<<<dim3(LD_ / 128, G_ / 128), 256, SMEM_SZ, s1>>>(
        w_ih, gwnt, wc16, LD_, D_);
    k_cvt<<<(G_ * D_ + 255) / 256, 256, 0, s1>>>(w_hh, hh, G_ * D_);
    k_zero_i<<<(B_ * N_ + 255) / 256, 256, 0, s1>>>(cnt, B_ * N_);
    k_count<<<(B_ * E_ + 255) / 256, 256, 0, s1>>>(edst, cnt);
    k_prefix<<<B_, N_, 0, s1>>>(cnt, off, pos);
    k_fill<<<(B_ * E_ + 255) / 256, 256, 0, s1>>>(esrc, edst, ew, pos, src_s, w_s);
    cudaEventRecord(eW, s1);

    // ---- main stream: fw cvt, embed, fusion GEMM ----
    k_cvt_t<<<(F_ * D_ + 255) / 256, 256>>>(fusion_w, fw, F_, D_);
    k_embed<<<M_, 192>>>(node_types, tok_ids, tok_lens, type_table, word_emb, fused);
    bmma<<<dim3(D_ / 128, M_ / 128), 256, SMEM_SZ>>>(fused, fw, fusion_b, h, D_, F_);

    cudaStreamWaitEvent(0, eW, 0);

    for (int l = 0; l < L_; ++l) {
        // fork gh onto side stream (depends only on h)
        cudaEventRecord(eH, 0);
        cudaStreamWaitEvent(s1, eH, 0);
        bmma<<<dim3(G_ / 128, M_ / 128), 256, SMEM_SZ, s1>>>(h, hh, b_hh, gh, G_, D_);
        cudaEventRecord(eG, s1);

        // main chain: q = gather(h) -> gi = q @ Wc[l] + b_ih
        k_gather<<<M_, 192>>>(off, src_s, w_s, h, q);
        bmma<<<dim3(G_ / 128, M_ / 128), 256, SMEM_SZ>>>(
            q, wc16 + (size_t)l * G_ * D_, b_ih, gi, G_, D_);

        cudaStreamWaitEvent(0, eG, 0);
        if (l < L_ - 1)
            k_gru<<<M_, 256>>>(gi, gh, h);
        else
            k_gru_out<<<M_, 256>>>(gi, gh, h, gnode_lens, out);
    }
}